// round 15
// baseline (speedup 1.0000x reference)
#include <cuda_runtime.h>
#include <cuda_bf16.h>
#include <cuda_fp16.h>
#include <cstdint>
#include <cstddef>

#define DDIM 4096
#define BATCH 2048
#define CAND_CAP (1u << 22)

// ---------------------------------------------------------------------------
// Device-global scratch
// ---------------------------------------------------------------------------
__device__ unsigned int g_hist[256];
__device__ unsigned int g_hist12[4096];
__device__ unsigned int g_prefix;
__device__ unsigned int g_krem;
__device__ float        g_thr;
__device__ unsigned int g_cand[CAND_CAP];
__device__ unsigned int g_cand_cnt;

__device__ __align__(128) __half g_W1h[(size_t)DDIM * DDIM];
__device__ __align__(128) __half g_W2h[(size_t)DDIM * DDIM];
__device__ __align__(128) __half g_W3h[(size_t)DDIM * DDIM];
__device__ __align__(128) __half g_Xh[(size_t)BATCH * DDIM];
__device__ __align__(128) __half g_H1h[(size_t)BATCH * DDIM];
__device__ __align__(128) __half g_H2h[(size_t)BATCH * DDIM];
__device__ float g_B1[DDIM];
__device__ float g_B2[DDIM];
__device__ float g_B3[DDIM];

// ---------------------------------------------------------------------------
// Radix select v3 (verified R11-R13): 12-bit plain-atomic hist (1 full pass)
// + compact (1 full pass) + cheap candidate-set passes for remaining 20 bits.
// ---------------------------------------------------------------------------
__device__ __forceinline__ unsigned int f2key(float f)
{
    unsigned int u = __float_as_uint(f);
    return (u & 0x80000000u) ? ~u : (u | 0x80000000u);
}

__global__ void rs_init(unsigned int k)
{
    int t = threadIdx.x;   // 1024
    if (t < 256) g_hist[t] = 0u;
    for (int i = t; i < 4096; i += 1024) g_hist12[i] = 0u;
    if (t == 0) { g_prefix = 0u; g_krem = k; g_cand_cnt = 0u; }
}

__global__ void rs_hist12(const float* __restrict__ p, int n4)
{
    __shared__ unsigned int sh[4096];
    for (int i = threadIdx.x; i < 4096; i += blockDim.x) sh[i] = 0u;
    __syncthreads();
    const float4* __restrict__ p4 = (const float4*)p;
    int i = blockIdx.x * blockDim.x + threadIdx.x;
    const int stride = gridDim.x * blockDim.x;
    for (; i < n4; i += stride) {
        float4 v = p4[i];
        atomicAdd(&sh[f2key(v.x) >> 20], 1u);
        atomicAdd(&sh[f2key(v.y) >> 20], 1u);
        atomicAdd(&sh[f2key(v.z) >> 20], 1u);
        atomicAdd(&sh[f2key(v.w) >> 20], 1u);
    }
    __syncthreads();
    for (int i2 = threadIdx.x; i2 < 4096; i2 += blockDim.x) {
        unsigned int cv = sh[i2];
        if (cv) atomicAdd(&g_hist12[i2], cv);
    }
}

__global__ void rs_scan4096(int shift)
{
    __shared__ unsigned int s[1024];
    const int t = threadIdx.x;   // 1024
    unsigned int c0 = g_hist12[4 * t + 0];
    unsigned int c1 = g_hist12[4 * t + 1];
    unsigned int c2 = g_hist12[4 * t + 2];
    unsigned int c3 = g_hist12[4 * t + 3];
    g_hist12[4 * t + 0] = 0u; g_hist12[4 * t + 1] = 0u;
    g_hist12[4 * t + 2] = 0u; g_hist12[4 * t + 3] = 0u;
    const unsigned int sum = c0 + c1 + c2 + c3;
    s[t] = sum;
    __syncthreads();
    #pragma unroll
    for (int off = 1; off < 1024; off <<= 1) {
        unsigned int add = (t >= off) ? s[t - off] : 0u;
        __syncthreads();
        s[t] += add;
        __syncthreads();
    }
    const unsigned int inc = s[t];
    const unsigned int exc = inc - sum;
    const unsigned int k   = g_krem;
    if (k >= exc && k < inc) {
        unsigned int run = exc, bin;
        if      (k < run + c0) { bin = 4u * t + 0u; }
        else if (k < (run += c0) + c1) { bin = 4u * t + 1u; }
        else if (k < (run += c1) + c2) { bin = 4u * t + 2u; }
        else    { run += c2;    bin = 4u * t + 3u; }
        g_prefix |= bin << shift;
        g_krem    = k - run;
    }
}

__global__ void rs_compact(const float* __restrict__ p, int n4)
{
    const unsigned int pref12 = g_prefix >> 20;
    const float4* __restrict__ p4 = (const float4*)p;
    const int stride = gridDim.x * blockDim.x;
    int i = blockIdx.x * blockDim.x + threadIdx.x;
    const int lane = threadIdx.x & 31;
    for (; i < n4; i += 2 * stride) {
        float4 v0 = p4[i];
        const bool has2 = (i + stride) < n4;
        float4 v1 = has2 ? p4[i + stride] : make_float4(0, 0, 0, 0);
        float arr[8] = {v0.x, v0.y, v0.z, v0.w, v1.x, v1.y, v1.z, v1.w};
        const int cnt = has2 ? 8 : 4;
        for (int c = 0; c < cnt; c++) {
            unsigned int key = f2key(arr[c]);
            bool m = (key >> 20) == pref12;
            unsigned int amask = __activemask();
            unsigned int bal = __ballot_sync(amask, m);
            if (m) {
                int leader = __ffs(bal) - 1;
                unsigned int base = 0;
                if (lane == leader)
                    base = atomicAdd(&g_cand_cnt, (unsigned int)__popc(bal));
                base = __shfl_sync(bal, base, leader);
                unsigned int idx = base + __popc(bal & ((1u << lane) - 1u));
                if (idx < CAND_CAP) g_cand[idx] = key;
            }
        }
    }
}

__global__ void rs_hist12c()
{
    __shared__ unsigned int sh[4096];
    for (int i = threadIdx.x; i < 4096; i += blockDim.x) sh[i] = 0u;
    __syncthreads();
    unsigned int n = g_cand_cnt;
    if (n > CAND_CAP) n = CAND_CAP;
    unsigned int i = blockIdx.x * blockDim.x + threadIdx.x;
    const unsigned int stride = gridDim.x * blockDim.x;
    for (; i < n; i += stride)
        atomicAdd(&sh[(g_cand[i] >> 8) & 0xFFFu], 1u);
    __syncthreads();
    for (int i2 = threadIdx.x; i2 < 4096; i2 += blockDim.x) {
        unsigned int cv = sh[i2];
        if (cv) atomicAdd(&g_hist12[i2], cv);
    }
}

__global__ void rs_histD()
{
    __shared__ unsigned int sh[256];
    for (int i = threadIdx.x; i < 256; i += blockDim.x) sh[i] = 0u;
    __syncthreads();
    const unsigned int pref24 = g_prefix >> 8;
    unsigned int n = g_cand_cnt;
    if (n > CAND_CAP) n = CAND_CAP;
    unsigned int i = blockIdx.x * blockDim.x + threadIdx.x;
    const unsigned int stride = gridDim.x * blockDim.x;
    for (; i < n; i += stride) {
        unsigned int key = g_cand[i];
        if ((key >> 8) == pref24) atomicAdd(&sh[key & 0xffu], 1u);
    }
    __syncthreads();
    for (int i2 = threadIdx.x; i2 < 256; i2 += blockDim.x) {
        unsigned int cv = sh[i2];
        if (cv) atomicAdd(&g_hist[i2], cv);
    }
}

__global__ void rs_pick()
{
    if (threadIdx.x == 0) {
        const unsigned int k = g_krem;
        unsigned int run = 0;
        for (int b = 0; b < 256; b++) {
            unsigned int c = g_hist[b];
            if (k < run + c) {
                unsigned int key = g_prefix | (unsigned int)b;
                unsigned int u = (key & 0x80000000u) ? (key ^ 0x80000000u) : ~key;
                g_thr = __uint_as_float(u);
                break;
            }
            run += c;
        }
    }
}

// ---------------------------------------------------------------------------
// mask / convert kernels
// ---------------------------------------------------------------------------
__global__ void mask_half(const float* __restrict__ w,
                          const float* __restrict__ s,
                          __half* __restrict__ out, int n4)
{
    const float thr = g_thr;
    const float4* __restrict__ w4 = (const float4*)w;
    const float4* __restrict__ s4 = (const float4*)s;
    uint2* __restrict__ o2 = (uint2*)out;
    int i = blockIdx.x * blockDim.x + threadIdx.x;
    const int stride = gridDim.x * blockDim.x;
    for (; i < n4; i += stride) {
        float4 wv = w4[i];
        float4 sv = s4[i];
        float f0 = (sv.x >= thr) ? wv.x : 0.0f;
        float f1 = (sv.y >= thr) ? wv.y : 0.0f;
        float f2 = (sv.z >= thr) ? wv.z : 0.0f;
        float f3 = (sv.w >= thr) ? wv.w : 0.0f;
        uint2 o;
        o.x = (unsigned int)__half_as_ushort(__float2half_rn(f0)) |
              ((unsigned int)__half_as_ushort(__float2half_rn(f1)) << 16);
        o.y = (unsigned int)__half_as_ushort(__float2half_rn(f2)) |
              ((unsigned int)__half_as_ushort(__float2half_rn(f3)) << 16);
        o2[i] = o;
    }
}

__global__ void conv_half(const float* __restrict__ in,
                          __half* __restrict__ out, int n4)
{
    const float4* __restrict__ p4 = (const float4*)in;
    uint2* __restrict__ o2 = (uint2*)out;
    int i = blockIdx.x * blockDim.x + threadIdx.x;
    const int stride = gridDim.x * blockDim.x;
    for (; i < n4; i += stride) {
        float4 v = p4[i];
        uint2 o;
        o.x = (unsigned int)__half_as_ushort(__float2half_rn(v.x)) |
              ((unsigned int)__half_as_ushort(__float2half_rn(v.y)) << 16);
        o.y = (unsigned int)__half_as_ushort(__float2half_rn(v.z)) |
              ((unsigned int)__half_as_ushort(__float2half_rn(v.w)) << 16);
        o2[i] = o;
    }
}

__global__ void mask_mul(const float* __restrict__ w,
                         const float* __restrict__ s,
                         float* __restrict__ out, int n4)
{
    const float thr = g_thr;
    const float4* __restrict__ w4 = (const float4*)w;
    const float4* __restrict__ s4 = (const float4*)s;
    float4* __restrict__ o4 = (float4*)out;
    int i = blockIdx.x * blockDim.x + threadIdx.x;
    const int stride = gridDim.x * blockDim.x;
    for (; i < n4; i += stride) {
        float4 wv = w4[i];
        float4 sv = s4[i];
        float4 r;
        r.x = (sv.x >= thr) ? wv.x : 0.0f;
        r.y = (sv.y >= thr) ? wv.y : 0.0f;
        r.z = (sv.z >= thr) ? wv.z : 0.0f;
        r.w = (sv.w >= thr) ? wv.w : 0.0f;
        o4[i] = r;
    }
}

// ---------------------------------------------------------------------------
// cp.async + ldmatrix + mma.sync (fp16)
// ---------------------------------------------------------------------------
__device__ __forceinline__ uint32_t smem_u32(const void* p)
{
    uint32_t a;
    asm("{ .reg .u64 t; cvta.to.shared.u64 t, %1; cvt.u32.u64 %0, t; }"
        : "=r"(a) : "l"(p));
    return a;
}

__device__ __forceinline__ void cpasync16(uint32_t dst, const void* src)
{
    asm volatile("cp.async.cg.shared.global [%0], [%1], 16;"
                 :: "r"(dst), "l"(src) : "memory");
}
#define CP_COMMIT() asm volatile("cp.async.commit_group;" ::: "memory")
#define CP_WAIT_1() asm volatile("cp.async.wait_group 1;" ::: "memory")

__device__ __forceinline__ void ldsm4(uint32_t& r0, uint32_t& r1,
                                      uint32_t& r2, uint32_t& r3, uint32_t a)
{
    asm volatile("ldmatrix.sync.aligned.m8n8.x4.shared.b16 {%0,%1,%2,%3}, [%4];"
                 : "=r"(r0), "=r"(r1), "=r"(r2), "=r"(r3) : "r"(a));
}

__device__ __forceinline__ void mma16816h(float* c,
                                          uint32_t a0, uint32_t a1,
                                          uint32_t a2, uint32_t a3,
                                          uint32_t b0, uint32_t b1)
{
    asm volatile(
        "mma.sync.aligned.m16n8k16.row.col.f32.f16.f16.f32 "
        "{%0,%1,%2,%3}, {%4,%5,%6,%7}, {%8,%9}, {%0,%1,%2,%3};"
        : "+f"(c[0]), "+f"(c[1]), "+f"(c[2]), "+f"(c[3])
        : "r"(a0), "r"(a1), "r"(a2), "r"(a3), "r"(b0), "r"(b1));
}

// ---------------------------------------------------------------------------
// fp16 single-pass HMMA GEMM: C = A@B^T + bias (opt ReLU)
// BK=64: 64 mainloop iterations (half the syncs of BK=32).
// Stage: A[128][64] @0 (16KB) + B[128][64] @16384 (16KB) = 32 KB/stage.
// 3 stages (96KB), prefetch depth 1 (wait_group 1); 2 CTAs/SM.
// SMEM rows are 128B (8 x 16B chunks), XOR swizzle ch ^= row&7 ->
// ldmatrix phases (8 distinct rows) hit 8 distinct chunks: conflict-free.
// Warp layout 4(M) x 2(N), warp tile 32x64 (verified R12/R13 mapping).
// ---------------------------------------------------------------------------
#define BM 128
#define BN 128
#define BK 64
#define GSTAGES 3
#define STG_B (2 * BM * BK * 2)        /* 32768 bytes per stage */
#define GSMEM  (GSTAGES * STG_B)       /* 98304 */

template<int RELU, int OUT_HALF>
__global__ void __launch_bounds__(256, 2) gemm_hmma(
    const __half* __restrict__ A,
    const __half* __restrict__ B,
    const float* __restrict__ bias,
    float* __restrict__ outf,
    __half* __restrict__ outh)
{
    extern __shared__ __align__(128) char smem[];
    const uint32_t sbase = smem_u32(smem);
    const int tid  = threadIdx.x;
    const int lane = tid & 31;
    const int wid  = tid >> 5;
    const int wm   = wid >> 1;          // 0..3  (M group, 32 rows each)
    const int wn   = wid & 1;           // 0..1  (N group, 64 cols each)
    const int bx   = blockIdx.x;        // N tile
    const int by   = blockIdx.y;        // M tile
    const int K    = DDIM;

    // loader mapping: 2 threads per 128B row; each thread owns 4 x 16B chunks
    const int lrow = tid >> 1;          // 0..127
    const int cb   = (tid & 1) * 4;     // chunk base: 0 or 4
    uint32_t dA[4], dB[4];
    #pragma unroll
    for (int c = 0; c < 4; c++) {
        const uint32_t sw = (uint32_t)(((cb + c) ^ (lrow & 7)) << 4);
        dA[c] = (uint32_t)lrow * 128 + sw;
        dB[c] = (uint32_t)lrow * 128 + sw + 16384u;
    }

    const int rowA = by * BM;
    const int rowB = bx * BN;
    const __half* sA = A + (size_t)(rowA + lrow) * K + cb * 8;
    const __half* sB = B + (size_t)(rowB + lrow) * K + cb * 8;

    #define LOAD_STAGE(stg, kt) do {                                          \
        const uint32_t s0 = sbase + (uint32_t)(stg) * STG_B;                  \
        const size_t ko = (size_t)(kt) * BK;                                  \
        cpasync16(s0 + dA[0], sA + ko);                                       \
        cpasync16(s0 + dA[1], sA + ko + 8);                                   \
        cpasync16(s0 + dA[2], sA + ko + 16);                                  \
        cpasync16(s0 + dA[3], sA + ko + 24);                                  \
        cpasync16(s0 + dB[0], sB + ko);                                       \
        cpasync16(s0 + dB[1], sB + ko + 8);                                   \
        cpasync16(s0 + dB[2], sB + ko + 16);                                  \
        cpasync16(s0 + dB[3], sB + ko + 24);                                  \
    } while (0)

    float c[2][8][4];
    #pragma unroll
    for (int i = 0; i < 2; i++)
        #pragma unroll
        for (int j = 0; j < 8; j++)
            #pragma unroll
            for (int q = 0; q < 4; q++) c[i][j][q] = 0.0f;

    const int NT = K / BK;              // 64

    LOAD_STAGE(0, 0); CP_COMMIT();
    LOAD_STAGE(1, 1); CP_COMMIT();

    const int fr = lane & 15;
    const int fh = lane >> 4;

    for (int t = 0; t < NT; t++) {
        CP_WAIT_1();
        __syncthreads();

        const int lt = t + GSTAGES - 1;
        if (lt < NT) LOAD_STAGE(lt % GSTAGES, lt);
        CP_COMMIT();

        const uint32_t sb = sbase + (uint32_t)(t % GSTAGES) * STG_B;

        #pragma unroll
        for (int kk = 0; kk < 4; kk++) {
            const int chb = kk * 2 + fh;   // chunk index 0..7

            uint32_t aoff[2], boff[4];
            #pragma unroll
            for (int mi = 0; mi < 2; mi++) {
                const int row = wm * 32 + mi * 16 + fr;
                aoff[mi] = (uint32_t)row * 128 +
                           (uint32_t)((chb ^ (row & 7)) << 4);
            }
            #pragma unroll
            for (int nj = 0; nj < 4; nj++) {
                const int row = wn * 64 + nj * 16 + fr;
                boff[nj] = (uint32_t)row * 128 +
                           (uint32_t)((chb ^ (row & 7)) << 4);
            }

            uint32_t b[4][4];
            #pragma unroll
            for (int nj = 0; nj < 4; nj++)
                ldsm4(b[nj][0], b[nj][1], b[nj][2], b[nj][3],
                      sb + 16384u + boff[nj]);

            #pragma unroll
            for (int mi = 0; mi < 2; mi++) {
                uint32_t a0, a1, a2, a3;
                ldsm4(a0, a1, a2, a3, sb + aoff[mi]);
                #pragma unroll
                for (int nj = 0; nj < 4; nj++) {
                    mma16816h(c[mi][2 * nj + 0], a0, a1, a2, a3,
                              b[nj][0], b[nj][2]);
                    mma16816h(c[mi][2 * nj + 1], a0, a1, a2, a3,
                              b[nj][1], b[nj][3]);
                }
            }
        }
    }

    // --- epilogue: bias (+ReLU), then fp32 store or fp16 store ---
    const int q   = lane >> 2;          // 0..7
    const int rp  = lane & 3;           // column pair
    const int m0g = by * BM + wm * 32;
    const int n0g = bx * BN + wn * 64;

    #pragma unroll
    for (int mi = 0; mi < 2; mi++) {
        #pragma unroll
        for (int ni = 0; ni < 8; ni++) {
            const int col = n0g + ni * 8 + rp * 2;
            const float bv0 = __ldg(bias + col);
            const float bv1 = __ldg(bias + col + 1);
            float v0 = c[mi][ni][0] + bv0;
            float v1 = c[mi][ni][1] + bv1;
            float v2 = c[mi][ni][2] + bv0;
            float v3 = c[mi][ni][3] + bv1;
            if (RELU) {
                v0 = fmaxf(v0, 0.0f); v1 = fmaxf(v1, 0.0f);
                v2 = fmaxf(v2, 0.0f); v3 = fmaxf(v3, 0.0f);
            }
            const int r0 = m0g + mi * 16 + q;
            const int r1 = r0 + 8;
            if (OUT_HALF) {
                unsigned int h0 =
                    (unsigned int)__half_as_ushort(__float2half_rn(v0)) |
                    ((unsigned int)__half_as_ushort(__float2half_rn(v1)) << 16);
                unsigned int h1 =
                    (unsigned int)__half_as_ushort(__float2half_rn(v2)) |
                    ((unsigned int)__half_as_ushort(__float2half_rn(v3)) << 16);
                *(unsigned int*)(outh + (size_t)r0 * DDIM + col) = h0;
                *(unsigned int*)(outh + (size_t)r1 * DDIM + col) = h1;
            } else {
                *(float2*)(outf + (size_t)r0 * DDIM + col) = make_float2(v0, v1);
                *(float2*)(outf + (size_t)r1 * DDIM + col) = make_float2(v2, v3);
            }
        }
    }
    #undef LOAD_STAGE
}

// ---------------------------------------------------------------------------
// kernel_launch
// ---------------------------------------------------------------------------
extern "C" void kernel_launch(void* const* d_in, const int* in_sizes, int n_in,
                              void* d_out, int out_size)
{
    const float* x   = (const float*)d_in[0];
    const float* w1  = (const float*)d_in[1];
    const float* b1  = (const float*)d_in[2];
    const float* w2  = (const float*)d_in[3];
    const float* b2  = (const float*)d_in[4];
    const float* w3  = (const float*)d_in[5];
    const float* b3  = (const float*)d_in[6];
    const float* sw1 = (const float*)d_in[7];
    const float* sb1 = (const float*)d_in[8];
    const float* sw2 = (const float*)d_in[9];
    const float* sb2 = (const float*)d_in[10];
    const float* sw3 = (const float*)d_in[11];
    const float* sb3 = (const float*)d_in[12];
    float* out = (float*)d_out;

    const int M = in_sizes[0] / DDIM;   // 2048

    long long total = 0;
    for (int i = 7; i <= 12; i++) total += (long long)in_sizes[i];
    const unsigned int j = (unsigned int)(total / 2);

    const int nW4 = (DDIM * DDIM) / 4;
    const int nB4 = DDIM / 4;
    const int nX4 = (M * DDIM) / 4;

    // --- 1) exact global threshold: 12-bit hist + compact + tail passes ---
    rs_init<<<1, 1024>>>(j);
    rs_hist12<<<1024, 256>>>(sw1, nW4);
    rs_hist12<<<1024, 256>>>(sw2, nW4);
    rs_hist12<<<1024, 256>>>(sw3, nW4);
    rs_hist12<<<4,    256>>>(sb1, nB4);
    rs_hist12<<<4,    256>>>(sb2, nB4);
    rs_hist12<<<4,    256>>>(sb3, nB4);
    rs_scan4096<<<1, 1024>>>(20);
    rs_compact<<<1024, 256>>>(sw1, nW4);
    rs_compact<<<1024, 256>>>(sw2, nW4);
    rs_compact<<<1024, 256>>>(sw3, nW4);
    rs_compact<<<4,    256>>>(sb1, nB4);
    rs_compact<<<4,    256>>>(sb2, nB4);
    rs_compact<<<4,    256>>>(sb3, nB4);
    rs_hist12c<<<256, 256>>>();
    rs_scan4096<<<1, 1024>>>(8);
    rs_histD<<<64, 256>>>();
    rs_pick<<<1, 32>>>();

    // --- scratch symbol addresses ---
    __half *pW1, *pW2, *pW3, *pXh, *pH1h, *pH2h;
    float *pB1, *pB2, *pB3;
    cudaGetSymbolAddress((void**)&pW1,  g_W1h);
    cudaGetSymbolAddress((void**)&pW2,  g_W2h);
    cudaGetSymbolAddress((void**)&pW3,  g_W3h);
    cudaGetSymbolAddress((void**)&pXh,  g_Xh);
    cudaGetSymbolAddress((void**)&pH1h, g_H1h);
    cudaGetSymbolAddress((void**)&pH2h, g_H2h);
    cudaGetSymbolAddress((void**)&pB1,  g_B1);
    cudaGetSymbolAddress((void**)&pB2,  g_B2);
    cudaGetSymbolAddress((void**)&pB3,  g_B3);

    // --- 2) masked weights -> fp16 ; masked biases fp32 ; convert x ---
    mask_half<<<1024, 256>>>(w1, sw1, pW1, nW4);
    mask_half<<<1024, 256>>>(w2, sw2, pW2, nW4);
    mask_half<<<1024, 256>>>(w3, sw3, pW3, nW4);
    mask_mul<<<4, 256>>>(b1, sb1, pB1, nB4);
    mask_mul<<<4, 256>>>(b2, sb2, pB2, nB4);
    mask_mul<<<4, 256>>>(b3, sb3, pB3, nB4);
    conv_half<<<1024, 256>>>(x, pXh, nX4);

    // --- 3) three dependent single-pass fp16 HMMA GEMMs (BK=64) ---
    cudaFuncSetAttribute(gemm_hmma<1, 1>,
                         cudaFuncAttributeMaxDynamicSharedMemorySize, GSMEM);
    cudaFuncSetAttribute(gemm_hmma<0, 0>,
                         cudaFuncAttributeMaxDynamicSharedMemorySize, GSMEM);

    dim3 grid(DDIM / BN, M / BM);       // (32, 16)
    gemm_hmma<1, 1><<<grid, 256, GSMEM>>>(pXh,  pW1, pB1, nullptr, pH1h);
    gemm_hmma<1, 1><<<grid, 256, GSMEM>>>(pH1h, pW2, pB2, nullptr, pH2h);
    gemm_hmma<0, 0><<<grid, 256, GSMEM>>>(pH2h, pW3, pB3, out, nullptr);

    (void)n_in; (void)out_size;
}